// round 12
// baseline (speedup 1.0000x reference)
#include <cuda_runtime.h>
#include <cuda_bf16.h>
#include <cstdint>

#define NN   10000
#define NE   160000
#define NCH  16
#define CQ   80        // c*5+q  (chunk K dimension; fr-major reorder)
#define OPD  80        // o*5+p  (GEMM N)
#define NFR  10        // f*2+r
#define NCHUNK 10      // chunk index == fr; K = fr*80 + cq
#define TEB  128       // edges per block (GEMM M)
#define THR  256
#define XAS  88        // xa row stride in words (hi/lo interleaved; conflict-free)
#define BRS  40        // B row stride in words

// ---------------- device scratch (allocation-free) ----------------
__device__ __align__(16) float g_y1[NN * OPD];
__device__ __align__(16) float g_h [NN * OPD];
__device__ __align__(16) float g_y2[NN * OPD];
__device__ __align__(16) float g_Wst1[CQ * OPD];
__device__ __align__(16) float g_Wst2[CQ * OPD];
#define BCH (80 * 80)   // halfwords per B chunk
__device__ __align__(16) unsigned short g_Bh1[NCHUNK * BCH];
__device__ __align__(16) unsigned short g_Bl1[NCHUNK * BCH];
__device__ __align__(16) unsigned short g_Bh2[NCHUNK * BCH];
__device__ __align__(16) unsigned short g_Bl2[NCHUNK * BCH];

// ---------------- SMEM map (bytes) ----------------
#define OFF_DST  0          // 128 int
#define OFF_PRE  512        // 128x10 f32 = 5120
#define OFF_XA   5632       // 128x88 words = 45056 (bf16 hi/lo interleaved A)
#define OFF_BH   50688      // 80x40 words = 12800
#define OFF_BL   63488      // 12800
#define SMEM_TOT 76288

// marker: shifts ncu's fixed capture ordinal by one so edge_gemm_tc gets profiled
__global__ void zz_marker() {}

// mma.sync m16n8k16 bf16 -> f32
static __device__ __forceinline__ void hmma(float* c, const uint32_t* a, const uint32_t* b) {
    asm volatile(
        "mma.sync.aligned.m16n8k16.row.col.f32.bf16.bf16.f32 "
        "{%0,%1,%2,%3}, {%4,%5,%6,%7}, {%8,%9}, {%0,%1,%2,%3};"
        : "+f"(c[0]), "+f"(c[1]), "+f"(c[2]), "+f"(c[3])
        : "r"(a[0]), "r"(a[1]), "r"(a[2]), "r"(a[3]), "r"(b[0]), "r"(b[1]));
}
// d = a*b + 0 (fresh accumulator, no clear needed)
static __device__ __forceinline__ void hmma_z(float* d, const uint32_t* a, const uint32_t* b) {
    asm volatile(
        "mma.sync.aligned.m16n8k16.row.col.f32.bf16.bf16.f32 "
        "{%0,%1,%2,%3}, {%4,%5,%6,%7}, {%8,%9}, {%10,%10,%10,%10};"
        : "=f"(d[0]), "=f"(d[1]), "=f"(d[2]), "=f"(d[3])
        : "r"(a[0]), "r"(a[1]), "r"(a[2]), "r"(a[3]), "r"(b[0]), "r"(b[1]), "f"(0.0f));
}
static __device__ __forceinline__ uint32_t pack_hi(float v0, float v1) {
    return __byte_perm(__float_as_uint(v0), __float_as_uint(v1), 0x7632);
}
static __device__ __forceinline__ uint32_t pack_lo(float v0, float v1) {
    float h0 = __uint_as_float(__float_as_uint(v0) & 0xFFFF0000u);
    float h1 = __uint_as_float(__float_as_uint(v1) & 0xFFFF0000u);
    float l0 = v0 - h0, l1 = v1 - h1;
    uint32_t r;
    asm("cvt.rn.bf16x2.f32 %0, %1, %2;" : "=r"(r) : "f"(l1), "f"(l0));
    return r;
}

// ---- prep: Ws relayout + W split bf16 hi/lo, fr-major, word-interleaved ----
__global__ void prep_weights(const float* __restrict__ W1, const float* __restrict__ W2,
                             const float* __restrict__ Ws1, const float* __restrict__ Ws2) {
    int i = blockIdx.x * blockDim.x + threadIdx.x;
    if (i < NCHUNK * BCH) {
        int c = i / BCH, rem = i % BCH;
        int n = rem / CQ, kk = rem % CQ;        // kk = cq
        int f = c >> 1, r = c & 1;
        int cc = kk / 5, q = kk % 5;
        int o = n / 5, p = n % 5;
        int src = ((((o * NCH + cc) * 5 + p) * 5 + q) * 5 + f) * 2 + r;
        float w1 = W1[src], w2 = W2[src];
        // word interleave inside each 16-k group so (b0,b1) is one LDS.64
        int s = kk / 16, j = kk % 16;
        int wo = j >> 1, par = j & 1;
        int wn2 = (wo < 4) ? (2 * wo) : (2 * (wo - 4) + 1);
        int hidx = (c * 80 + n) * CQ + s * 16 + wn2 * 2 + par;
        __nv_bfloat16 h1 = __float2bfloat16_rn(w1);
        __nv_bfloat16 l1 = __float2bfloat16_rn(w1 - __bfloat162float(h1));
        __nv_bfloat16 h2 = __float2bfloat16_rn(w2);
        __nv_bfloat16 l2 = __float2bfloat16_rn(w2 - __bfloat162float(h2));
        g_Bh1[hidx] = __bfloat16_as_ushort(h1);
        g_Bl1[hidx] = __bfloat16_as_ushort(l1);
        g_Bh2[hidx] = __bfloat16_as_ushort(h2);
        g_Bl2[hidx] = __bfloat16_as_ushort(l2);
    }
    if (i < CQ * OPD) {
        int op = i % OPD, cq = i / OPD;
        int o = op / 5, p = op % 5, c = cq / 5, q = cq % 5;
        int src = ((o * NCH + c) * 5 + p) * 5 + q;
        g_Wst1[i] = Ws1[src];
        g_Wst2[i] = Ws2[src];
    }
}

// ---- self-interaction (fp32, initializes y incl. bias) ----
__global__ __launch_bounds__(80) void self_gemm(const float* __restrict__ x,
                                                const float* __restrict__ Wst,
                                                const float* __restrict__ b,
                                                float* __restrict__ y) {
    __shared__ float xs[4][CQ];
    int n0 = blockIdx.x * 4;
    int t = threadIdx.x;
#pragma unroll
    for (int j = 0; j < 4; ++j) xs[j][t] = x[(n0 + j) * CQ + t];
    __syncthreads();
    float bias = ((t % 5) == 0) ? b[t / 5] : 0.f;
    float a0 = bias, a1 = bias, a2 = bias, a3 = bias;
#pragma unroll 8
    for (int k = 0; k < CQ; ++k) {
        float w = __ldg(&Wst[k * OPD + t]);
        a0 = fmaf(xs[0][k], w, a0);
        a1 = fmaf(xs[1][k], w, a1);
        a2 = fmaf(xs[2][k], w, a2);
        a3 = fmaf(xs[3][k], w, a3);
    }
    y[(n0 + 0) * OPD + t] = a0;
    y[(n0 + 1) * OPD + t] = a1;
    y[(n0 + 2) * OPD + t] = a2;
    y[(n0 + 3) * OPD + t] = a3;
}

// ---- HMMA edge GEMM: G_c = Xt*Wc^T on tensor pipe; acc += pre[:,c] ⊙ G_c ----
// nf range split into two passes per chunk to keep tmp<=24 regs (no spills).
__global__ __launch_bounds__(THR, 2) void edge_gemm_tc(
    const float* __restrict__ xin,
    const int*   __restrict__ ei,
    const float* __restrict__ precomp,
    const float* __restrict__ conn,
    const unsigned short* __restrict__ Bgh,
    const unsigned short* __restrict__ Bgl,
    float* __restrict__ y)
{
    extern __shared__ unsigned char smem[];
    int*      dst_s = (int*)(smem + OFF_DST);
    float*    pres  = (float*)(smem + OFF_PRE);   // [128][10]
    uint32_t* xa    = (uint32_t*)(smem + OFF_XA); // [128][88] interleaved (hi,lo) bf16x2
    uint32_t* Bh    = (uint32_t*)(smem + OFF_BH); // [80][40]
    uint32_t* Bl    = (uint32_t*)(smem + OFF_BL);

    const int tid = threadIdx.x;
    const int e    = tid >> 1, half = tid & 1;
    const int eg   = blockIdx.x * TEB + e;

    // ---- phase 1: gather + transport + bf16 hi/lo split (2 threads/edge) ----
    {
        int src = ei[2 * eg];
        if (!half) dst_s[e] = ei[2 * eg + 1];
        float phi = conn[eg];
        float s1, c1, s2, c2;
        __sincosf(phi, &s1, &c1);
        __sincosf(2.f * phi, &s2, &c2);
        const float4* xr = (const float4*)(xin + (long long)src * CQ);
        float v[40];   // this thread's 40 cq values (cq in [40*half, 40*half+40))
#pragma unroll
        for (int g = 0; g < 2; ++g) {
            int c4 = 2 * half + g;
            float t[20];
#pragma unroll
            for (int j = 0; j < 5; ++j) {
                float4 t4 = xr[c4 * 5 + j];
                t[4*j] = t4.x; t[4*j+1] = t4.y; t[4*j+2] = t4.z; t[4*j+3] = t4.w;
            }
#pragma unroll
            for (int cc = 0; cc < 4; ++cc) {
                int lc = g * 4 + cc;  // local channel 0..7
                float m0 = t[cc*5], x1 = t[cc*5+1], x2 = t[cc*5+2], x3 = t[cc*5+3], x4 = t[cc*5+4];
                v[lc*5 + 0] = m0;
                v[lc*5 + 1] = c1 * x1 - s1 * x2;
                v[lc*5 + 2] = s1 * x1 + c1 * x2;
                v[lc*5 + 3] = c2 * x3 - s2 * x4;
                v[lc*5 + 4] = s2 * x3 + c2 * x4;
            }
        }
        // pack into interleaved (hi,lo) bf16x2 word pairs
        uint32_t base = e * XAS + half * 40;
#pragma unroll
        for (int j2 = 0; j2 < 20; ++j2) {
            uint2 w;
            w.x = pack_hi(v[2*j2], v[2*j2+1]);
            w.y = pack_lo(v[2*j2], v[2*j2+1]);
            *(uint2*)&xa[base + 2*j2] = w;
        }
    }
    for (int i = tid; i < TEB * NFR; i += THR)
        pres[i] = precomp[(long long)blockIdx.x * TEB * NFR + i];
    __syncthreads();

    // warp tiling: 8 warps = 4 M-tiles(32) x 2 N-tiles(40)
    const int wid = tid >> 5, lid = tid & 31;
    const int wm = wid & 3, wn = wid >> 2;
    const int lg = lid >> 2, lt = lid & 3;

    int rr[4];
#pragma unroll
    for (int i = 0; i < 4; ++i) rr[i] = wm * 32 + 8 * i + lg;

    float acc[2][5][4];
#pragma unroll
    for (int m = 0; m < 2; ++m)
#pragma unroll
        for (int nf = 0; nf < 5; ++nf)
#pragma unroll
            for (int j = 0; j < 4; ++j) acc[m][nf][j] = 0.f;

#pragma unroll 1
    for (int c = 0; c < NCHUNK; ++c) {
        if (c) __syncthreads();
        // stage B hi/lo chunk
        {
            const uint4* sh = (const uint4*)(Bgh + c * BCH);
            const uint4* sl = (const uint4*)(Bgl + c * BCH);
            uint4* dh = (uint4*)Bh;
            uint4* dl = (uint4*)Bl;
#pragma unroll
            for (int i = 0; i < 4; ++i) {
                int idx = tid + i * THR;
                if (idx < 800) { dh[idx] = sh[idx]; dl[idx] = sl[idx]; }
            }
        }
        float prr[4];
#pragma unroll
        for (int i = 0; i < 4; ++i) prr[i] = pres[rr[i] * NFR + c];
        __syncthreads();

        // ---- pass 0: nf = 0..2 (tmp 24 regs) ----
        {
            float tmp[2][3][4];
#pragma unroll
            for (int s = 0; s < 5; ++s) {
                uint32_t ah[2][4], al[2][4];
#pragma unroll
                for (int m = 0; m < 2; ++m) {
                    int r0 = rr[2*m] * XAS, r1 = rr[2*m+1] * XAS;
                    int kw = 2 * (s * 8 + lt);
                    uint2 a00 = *(const uint2*)&xa[r0 + kw];
                    uint2 a10 = *(const uint2*)&xa[r1 + kw];
                    uint2 a02 = *(const uint2*)&xa[r0 + kw + 8];
                    uint2 a12 = *(const uint2*)&xa[r1 + kw + 8];
                    ah[m][0] = a00.x; ah[m][1] = a10.x; ah[m][2] = a02.x; ah[m][3] = a12.x;
                    al[m][0] = a00.y; al[m][1] = a10.y; al[m][2] = a02.y; al[m][3] = a12.y;
                }
#pragma unroll
                for (int nf = 0; nf < 3; ++nf) {
                    int bw = (wn * 40 + nf * 8 + lg) * BRS + s * 8 + 2 * lt;
                    uint2 th = *(const uint2*)&Bh[bw];
                    uint2 tl = *(const uint2*)&Bl[bw];
                    uint32_t bh2[2] = {th.x, th.y}, bl2[2] = {tl.x, tl.y};
#pragma unroll
                    for (int m = 0; m < 2; ++m) {
                        if (s == 0) hmma_z(tmp[m][nf], ah[m], bh2);
                        else        hmma  (tmp[m][nf], ah[m], bh2);
                        hmma(tmp[m][nf], ah[m], bl2);
                        hmma(tmp[m][nf], al[m], bh2);
                    }
                }
            }
#pragma unroll
            for (int m = 0; m < 2; ++m)
#pragma unroll
                for (int nf = 0; nf < 3; ++nf) {
                    acc[m][nf][0] = fmaf(prr[2*m],     tmp[m][nf][0], acc[m][nf][0]);
                    acc[m][nf][1] = fmaf(prr[2*m],     tmp[m][nf][1], acc[m][nf][1]);
                    acc[m][nf][2] = fmaf(prr[2*m + 1], tmp[m][nf][2], acc[m][nf][2]);
                    acc[m][nf][3] = fmaf(prr[2*m + 1], tmp[m][nf][3], acc[m][nf][3]);
                }
        }
        // ---- pass 1: nf = 3..4 (tmp 16 regs) ----
        {
            float tmp[2][2][4];
#pragma unroll
            for (int s = 0; s < 5; ++s) {
                uint32_t ah[2][4], al[2][4];
#pragma unroll
                for (int m = 0; m < 2; ++m) {
                    int r0 = rr[2*m] * XAS, r1 = rr[2*m+1] * XAS;
                    int kw = 2 * (s * 8 + lt);
                    uint2 a00 = *(const uint2*)&xa[r0 + kw];
                    uint2 a10 = *(const uint2*)&xa[r1 + kw];
                    uint2 a02 = *(const uint2*)&xa[r0 + kw + 8];
                    uint2 a12 = *(const uint2*)&xa[r1 + kw + 8];
                    ah[m][0] = a00.x; ah[m][1] = a10.x; ah[m][2] = a02.x; ah[m][3] = a12.x;
                    al[m][0] = a00.y; al[m][1] = a10.y; al[m][2] = a02.y; al[m][3] = a12.y;
                }
#pragma unroll
                for (int nf = 0; nf < 2; ++nf) {
                    int bw = (wn * 40 + (nf + 3) * 8 + lg) * BRS + s * 8 + 2 * lt;
                    uint2 th = *(const uint2*)&Bh[bw];
                    uint2 tl = *(const uint2*)&Bl[bw];
                    uint32_t bh2[2] = {th.x, th.y}, bl2[2] = {tl.x, tl.y};
#pragma unroll
                    for (int m = 0; m < 2; ++m) {
                        if (s == 0) hmma_z(tmp[m][nf], ah[m], bh2);
                        else        hmma  (tmp[m][nf], ah[m], bh2);
                        hmma(tmp[m][nf], ah[m], bl2);
                        hmma(tmp[m][nf], al[m], bh2);
                    }
                }
            }
#pragma unroll
            for (int m = 0; m < 2; ++m)
#pragma unroll
                for (int nf = 0; nf < 2; ++nf) {
                    acc[m][nf + 3][0] = fmaf(prr[2*m],     tmp[m][nf][0], acc[m][nf + 3][0]);
                    acc[m][nf + 3][1] = fmaf(prr[2*m],     tmp[m][nf][1], acc[m][nf + 3][1]);
                    acc[m][nf + 3][2] = fmaf(prr[2*m + 1], tmp[m][nf][2], acc[m][nf + 3][2]);
                    acc[m][nf + 3][3] = fmaf(prr[2*m + 1], tmp[m][nf][3], acc[m][nf + 3][3]);
                }
        }
    }

    // ---- epilogue: scatter C fragments (col pairs contiguous) ----
#pragma unroll
    for (int m = 0; m < 2; ++m) {
        int r0 = wm * 32 + m * 16 + lg;
        int r1 = r0 + 8;
        long long d0 = dst_s[r0], d1 = dst_s[r1];
#pragma unroll
        for (int nf = 0; nf < 5; ++nf) {
            int col = wn * 40 + nf * 8 + 2 * lt;
            asm volatile("red.global.add.v2.f32 [%0], {%1, %2};"
                         :: "l"(y + d0 * OPD + col), "f"(acc[m][nf][0]), "f"(acc[m][nf][1])
                         : "memory");
            asm volatile("red.global.add.v2.f32 [%0], {%1, %2};"
                         :: "l"(y + d1 * OPD + col), "f"(acc[m][nf][2]), "f"(acc[m][nf][3])
                         : "memory");
        }
    }
}

// ---- Fourier -> samples -> ReLU -> Fourier (K=7, order 2), optional residual ----
__global__ void nonlin_kernel(const float* __restrict__ in,
                              const float* __restrict__ resid,
                              float* __restrict__ out) {
    int i = blockIdx.x * blockDim.x + threadIdx.x;
    if (i >= NN * NCH) return;
    float v0 = in[i*5+0], v1 = in[i*5+1], v2 = in[i*5+2], v3 = in[i*5+3], v4 = in[i*5+4];
    if (resid) {
        v0 += resid[i*5+0]; v1 += resid[i*5+1]; v2 += resid[i*5+2];
        v3 += resid[i*5+3]; v4 += resid[i*5+4];
    }
    float o0 = 0.f, o1 = 0.f, o2 = 0.f, o3 = 0.f, o4 = 0.f;
#pragma unroll
    for (int k = 0; k < 7; ++k) {
        float th = 0.8975979010256552f * (float)k;
        float s1, c1, s2, c2;
        __sincosf(th, &s1, &c1);
        __sincosf(2.f * th, &s2, &c2);
        float s = v0 + c1*v1 + s1*v2 + c2*v3 + s2*v4;
        s = fmaxf(s, 0.f);
        o0 += s; o1 += s*c1; o2 += s*s1; o3 += s*c2; o4 += s*s2;
    }
    out[i*5+0] = o0 * (1.f/7.f);
    out[i*5+1] = o1 * (2.f/7.f);
    out[i*5+2] = o2 * (2.f/7.f);
    out[i*5+3] = o3 * (2.f/7.f);
    out[i*5+4] = o4 * (2.f/7.f);
}

extern "C" void kernel_launch(void* const* d_in, const int* in_sizes, int n_in,
                              void* d_out, int out_size) {
    const float* x    = (const float*)d_in[0];
    const int*   ei   = (const int*)d_in[1];   // int32 (JAX x64 disabled)
    const float* pre  = (const float*)d_in[2];
    const float* conn = (const float*)d_in[3];
    const float* W1   = (const float*)d_in[4];
    const float* b1   = (const float*)d_in[5];
    const float* Ws1  = (const float*)d_in[6];
    const float* W2   = (const float*)d_in[7];
    const float* b2   = (const float*)d_in[8];
    const float* Ws2  = (const float*)d_in[9];
    float* out = (float*)d_out;

    cudaFuncSetAttribute(edge_gemm_tc, cudaFuncAttributeMaxDynamicSharedMemorySize, SMEM_TOT);

    float *y1, *h, *y2, *Wst1, *Wst2;
    unsigned short *Bh1, *Bl1, *Bh2, *Bl2;
    cudaGetSymbolAddress((void**)&y1,   g_y1);
    cudaGetSymbolAddress((void**)&h,    g_h);
    cudaGetSymbolAddress((void**)&y2,   g_y2);
    cudaGetSymbolAddress((void**)&Wst1, g_Wst1);
    cudaGetSymbolAddress((void**)&Wst2, g_Wst2);
    cudaGetSymbolAddress((void**)&Bh1,  g_Bh1);
    cudaGetSymbolAddress((void**)&Bl1,  g_Bl1);
    cudaGetSymbolAddress((void**)&Bh2,  g_Bh2);
    cudaGetSymbolAddress((void**)&Bl2,  g_Bl2);

    // shift ncu's capture ordinal so an edge_gemm_tc launch lands under -c 1
    zz_marker<<<1, 32>>>();

    prep_weights<<<(NCHUNK * BCH + 255) / 256, 256>>>(W1, W2, Ws1, Ws2);

    // layer 1
    self_gemm<<<NN / 4, 80>>>(x, Wst1, b1, y1);
    edge_gemm_tc<<<NE / TEB, THR, SMEM_TOT>>>(x, ei, pre, conn, Bh1, Bl1, y1);
    nonlin_kernel<<<(NN * NCH + 127) / 128, 128>>>(y1, nullptr, h);

    // layer 2
    self_gemm<<<NN / 4, 80>>>(h, Wst2, b2, y2);
    edge_gemm_tc<<<NE / TEB, THR, SMEM_TOT>>>(h, ei, pre, conn, Bh2, Bl2, y2);

    // residual + final nonlin -> output
    nonlin_kernel<<<(NN * NCH + 127) / 128, 128>>>(y2, x, out);
}

// round 14
// speedup vs baseline: 1.4872x; 1.4872x over previous
#include <cuda_runtime.h>
#include <cuda_bf16.h>
#include <cstdint>

#define NN   10000
#define NE   160000
#define NCH  16
#define CQ   80        // c*5+q  (chunk K dimension; fr-major reorder)
#define OPD  80        // o*5+p  (GEMM N)
#define NFR  10        // f*2+r
#define NCHUNK 10      // chunk index == fr; K = fr*80 + cq
#define TEB  128       // edges per block (GEMM M)
#define THR  256
#define XTS  88        // xt row stride in floats (conflict-free LDS.64)

// ---------------- device scratch (allocation-free) ----------------
__device__ __align__(16) float g_y1[NN * OPD];
__device__ __align__(16) float g_h [NN * OPD];
__device__ __align__(16) float g_y2[NN * OPD];
__device__ __align__(16) float g_Wst1[CQ * OPD];
__device__ __align__(16) float g_Wst2[CQ * OPD];
// W bf16 hi/lo, fr-major chunks, dense rows, word-interleaved: [chunk][80 n][80 kk]
#define BCH (80 * 80)   // halfwords per chunk
__device__ __align__(16) unsigned short g_Bh1[NCHUNK * BCH];
__device__ __align__(16) unsigned short g_Bl1[NCHUNK * BCH];
__device__ __align__(16) unsigned short g_Bh2[NCHUNK * BCH];
__device__ __align__(16) unsigned short g_Bl2[NCHUNK * BCH];

// ---------------- SMEM map (bytes) ----------------
#define OFF_DST  0          // 128 int
#define OFF_PRE  512        // 128x10 f32 = 5120
#define OFF_XT   5632       // 128x88 f32 = 45056
#define SMEM_TOT 50688

// marker: keeps ncu's fixed capture ordinal on edge_gemm_tc
__global__ void zz_marker() {}

// mma.sync m16n8k16 bf16 -> f32 (base feature, compiles on compute_103)
static __device__ __forceinline__ void hmma(float* c, const uint32_t* a, const uint32_t* b) {
    asm volatile(
        "mma.sync.aligned.m16n8k16.row.col.f32.bf16.bf16.f32 "
        "{%0,%1,%2,%3}, {%4,%5,%6,%7}, {%8,%9}, {%0,%1,%2,%3};"
        : "+f"(c[0]), "+f"(c[1]), "+f"(c[2]), "+f"(c[3])
        : "r"(a[0]), "r"(a[1]), "r"(a[2]), "r"(a[3]), "r"(b[0]), "r"(b[1]));
}
static __device__ __forceinline__ uint32_t pack_hi(float v0, float v1) {
    return __byte_perm(__float_as_uint(v0), __float_as_uint(v1), 0x7632);
}
static __device__ __forceinline__ uint32_t pack_lo(float v0, float v1) {
    float h0 = __uint_as_float(__float_as_uint(v0) & 0xFFFF0000u);
    float h1 = __uint_as_float(__float_as_uint(v1) & 0xFFFF0000u);
    float l0 = v0 - h0, l1 = v1 - h1;
    uint32_t r;
    asm("cvt.rn.bf16x2.f32 %0, %1, %2;" : "=r"(r) : "f"(l1), "f"(l0));
    return r;
}

// ---- prep: Ws relayout + W split bf16 hi/lo, fr-major, word-interleaved ----
__global__ void prep_weights(const float* __restrict__ W1, const float* __restrict__ W2,
                             const float* __restrict__ Ws1, const float* __restrict__ Ws2) {
    int i = blockIdx.x * blockDim.x + threadIdx.x;
    if (i < NCHUNK * BCH) {
        int c = i / BCH, rem = i % BCH;
        int n = rem / CQ, kk = rem % CQ;        // kk = cq
        int f = c >> 1, r = c & 1;
        int cc = kk / 5, q = kk % 5;
        int o = n / 5, p = n % 5;
        int src = ((((o * NCH + cc) * 5 + p) * 5 + q) * 5 + f) * 2 + r;
        float w1 = W1[src], w2 = W2[src];
        // word interleave inside each 16-k group so (b0,b1) is one LDG.64
        int s = kk / 16, j = kk % 16;
        int wo = j >> 1, par = j & 1;
        int wn2 = (wo < 4) ? (2 * wo) : (2 * (wo - 4) + 1);
        int hidx = (c * 80 + n) * CQ + s * 16 + wn2 * 2 + par;
        __nv_bfloat16 h1 = __float2bfloat16_rn(w1);
        __nv_bfloat16 l1 = __float2bfloat16_rn(w1 - __bfloat162float(h1));
        __nv_bfloat16 h2 = __float2bfloat16_rn(w2);
        __nv_bfloat16 l2 = __float2bfloat16_rn(w2 - __bfloat162float(h2));
        g_Bh1[hidx] = __bfloat16_as_ushort(h1);
        g_Bl1[hidx] = __bfloat16_as_ushort(l1);
        g_Bh2[hidx] = __bfloat16_as_ushort(h2);
        g_Bl2[hidx] = __bfloat16_as_ushort(l2);
    }
    if (i < CQ * OPD) {
        int op = i % OPD, cq = i / OPD;
        int o = op / 5, p = op % 5, c = cq / 5, q = cq % 5;
        int src = ((o * NCH + c) * 5 + p) * 5 + q;
        g_Wst1[i] = Ws1[src];
        g_Wst2[i] = Ws2[src];
    }
}

// ---- self-interaction (fp32, initializes y incl. bias) ----
__global__ __launch_bounds__(80) void self_gemm(const float* __restrict__ x,
                                                const float* __restrict__ Wst,
                                                const float* __restrict__ b,
                                                float* __restrict__ y) {
    __shared__ float xs[4][CQ];
    int n0 = blockIdx.x * 4;
    int t = threadIdx.x;
#pragma unroll
    for (int j = 0; j < 4; ++j) xs[j][t] = x[(n0 + j) * CQ + t];
    __syncthreads();
    float bias = ((t % 5) == 0) ? b[t / 5] : 0.f;
    float a0 = bias, a1 = bias, a2 = bias, a3 = bias;
#pragma unroll 8
    for (int k = 0; k < CQ; ++k) {
        float w = __ldg(&Wst[k * OPD + t]);
        a0 = fmaf(xs[0][k], w, a0);
        a1 = fmaf(xs[1][k], w, a1);
        a2 = fmaf(xs[2][k], w, a2);
        a3 = fmaf(xs[3][k], w, a3);
    }
    y[(n0 + 0) * OPD + t] = a0;
    y[(n0 + 1) * OPD + t] = a1;
    y[(n0 + 2) * OPD + t] = a2;
    y[(n0 + 3) * OPD + t] = a3;
}

// ---- HMMA edge GEMM: barrier-free mainloop, B fragments via LDG (L1-resident) ----
__global__ __launch_bounds__(THR, 2) void edge_gemm_tc(
    const float* __restrict__ xin,
    const int*   __restrict__ ei,
    const float* __restrict__ precomp,
    const float* __restrict__ conn,
    const unsigned short* __restrict__ Bgh,
    const unsigned short* __restrict__ Bgl,
    float* __restrict__ y)
{
    extern __shared__ unsigned char smem[];
    int*      dst_s = (int*)(smem + OFF_DST);
    float*    pres  = (float*)(smem + OFF_PRE);   // [128][10]
    float*    xt    = (float*)(smem + OFF_XT);    // [128][88]

    const int tid = threadIdx.x;
    const int e    = tid >> 1, half = tid & 1;
    const int eg   = blockIdx.x * TEB + e;

    // ---- phase 1: gather + parallel transport (2 threads per edge) ----
    {
        int src = ei[2 * eg];
        if (!half) dst_s[e] = ei[2 * eg + 1];
        float phi = conn[eg];
        float s1, c1, s2, c2;
        __sincosf(phi, &s1, &c1);
        __sincosf(2.f * phi, &s2, &c2);
        const float4* xr = (const float4*)(xin + (long long)src * CQ);
#pragma unroll
        for (int g = 0; g < 2; ++g) {
            int c4 = 2 * half + g;
            float v[20];
#pragma unroll
            for (int j = 0; j < 5; ++j) {
                float4 t4 = xr[c4 * 5 + j];
                v[4*j] = t4.x; v[4*j+1] = t4.y; v[4*j+2] = t4.z; v[4*j+3] = t4.w;
            }
#pragma unroll
            for (int cc = 0; cc < 4; ++cc) {
                int c = c4 * 4 + cc;
                float m0 = v[cc*5], x1 = v[cc*5+1], x2 = v[cc*5+2], x3 = v[cc*5+3], x4 = v[cc*5+4];
                float* row = xt + e * XTS + c * 5;
                row[0] = m0;
                row[1] = c1 * x1 - s1 * x2;
                row[2] = s1 * x1 + c1 * x2;
                row[3] = c2 * x3 - s2 * x4;
                row[4] = s2 * x3 + c2 * x4;
            }
        }
    }
    for (int i = tid; i < TEB * NFR; i += THR)
        pres[i] = precomp[(long long)blockIdx.x * TEB * NFR + i];
    __syncthreads();   // ONLY barrier in the kernel

    // warp tiling: 8 warps = 4 M-tiles(32) x 2 N-tiles(40)
    const int wid = tid >> 5, lid = tid & 31;
    const int wm = wid & 3, wn = wid >> 2;
    const int lg = lid >> 2, lt = lid & 3;

    int rr[4];
#pragma unroll
    for (int i = 0; i < 4; ++i) rr[i] = wm * 32 + 8 * i + lg;

    float acc[2][5][4];
#pragma unroll
    for (int m = 0; m < 2; ++m)
#pragma unroll
        for (int nf = 0; nf < 5; ++nf)
#pragma unroll
            for (int j = 0; j < 4; ++j) acc[m][nf][j] = 0.f;

    // B fragment base (word units): row (wn*40+nf*8+lg), word s*8+2lt
    const unsigned short* bh_base = Bgh + 2 * ((wn * 40 + lg) * CQ / 2) * 1;  // computed below per-use
    (void)bh_base;

#pragma unroll 1
    for (int c = 0; c < NCHUNK; ++c) {
        float prr[4];
#pragma unroll
        for (int i = 0; i < 4; ++i) prr[i] = pres[rr[i] * NFR + c];

#pragma unroll
        for (int s = 0; s < 5; ++s) {
            const int ko = 16 * s + 2 * lt;
            // B fragments: LDG.64 from gmem (shared across warps -> L1 hits)
            uint32_t bh[5][2], bl[5][2];
#pragma unroll
            for (int nf = 0; nf < 5; ++nf) {
                int w = (c * 80 + wn * 40 + nf * 8 + lg) * CQ + s * 16 + 4 * lt;  // halfword idx
                uint2 th = __ldg((const uint2*)(Bgh + w));
                uint2 tl = __ldg((const uint2*)(Bgl + w));
                bh[nf][0] = th.x; bh[nf][1] = th.y;
                bl[nf][0] = tl.x; bl[nf][1] = tl.y;
            }
            // A fragments built in registers: V = pre[row,c] * xt[row][k]
            uint32_t ah[2][4], al[2][4];
#pragma unroll
            for (int m = 0; m < 2; ++m) {
#pragma unroll
                for (int i2 = 0; i2 < 2; ++i2) {
                    const float* xrow = xt + rr[2 * m + i2] * XTS;
                    float p = prr[2 * m + i2];
                    float2 x0 = *(const float2*)&xrow[ko];       // k lo pair
                    float2 x1 = *(const float2*)&xrow[ko + 8];   // k hi pair
                    float v00 = x0.x * p, v01 = x0.y * p;
                    float v10 = x1.x * p, v11 = x1.y * p;
                    ah[m][i2]     = pack_hi(v00, v01);
                    ah[m][i2 + 2] = pack_hi(v10, v11);
                    al[m][i2]     = pack_lo(v00, v01);
                    al[m][i2 + 2] = pack_lo(v10, v11);
                }
            }
#pragma unroll
            for (int m = 0; m < 2; ++m)
#pragma unroll
                for (int nf = 0; nf < 5; ++nf) {
                    hmma(acc[m][nf], ah[m], bh[nf]);
                    hmma(acc[m][nf], ah[m], bl[nf]);
                    hmma(acc[m][nf], al[m], bh[nf]);
                }
        }
    }

    // ---- epilogue: scatter C fragments (col pairs contiguous) ----
#pragma unroll
    for (int m = 0; m < 2; ++m) {
        int r0 = wm * 32 + m * 16 + lg;
        int r1 = r0 + 8;
        long long d0 = dst_s[r0], d1 = dst_s[r1];
#pragma unroll
        for (int nf = 0; nf < 5; ++nf) {
            int col = wn * 40 + nf * 8 + 2 * lt;
            asm volatile("red.global.add.v2.f32 [%0], {%1, %2};"
                         :: "l"(y + d0 * OPD + col), "f"(acc[m][nf][0]), "f"(acc[m][nf][1])
                         : "memory");
            asm volatile("red.global.add.v2.f32 [%0], {%1, %2};"
                         :: "l"(y + d1 * OPD + col), "f"(acc[m][nf][2]), "f"(acc[m][nf][3])
                         : "memory");
        }
    }
}

// ---- Fourier -> samples -> ReLU -> Fourier (K=7, order 2), optional residual ----
__global__ void nonlin_kernel(const float* __restrict__ in,
                              const float* __restrict__ resid,
                              float* __restrict__ out) {
    int i = blockIdx.x * blockDim.x + threadIdx.x;
    if (i >= NN * NCH) return;
    float v0 = in[i*5+0], v1 = in[i*5+1], v2 = in[i*5+2], v3 = in[i*5+3], v4 = in[i*5+4];
    if (resid) {
        v0 += resid[i*5+0]; v1 += resid[i*5+1]; v2 += resid[i*5+2];
        v3 += resid[i*5+3]; v4 += resid[i*5+4];
    }
    float o0 = 0.f, o1 = 0.f, o2 = 0.f, o3 = 0.f, o4 = 0.f;
#pragma unroll
    for (int k = 0; k < 7; ++k) {
        float th = 0.8975979010256552f * (float)k;
        float s1, c1, s2, c2;
        __sincosf(th, &s1, &c1);
        __sincosf(2.f * th, &s2, &c2);
        float s = v0 + c1*v1 + s1*v2 + c2*v3 + s2*v4;
        s = fmaxf(s, 0.f);
        o0 += s; o1 += s*c1; o2 += s*s1; o3 += s*c2; o4 += s*s2;
    }
    out[i*5+0] = o0 * (1.f/7.f);
    out[i*5+1] = o1 * (2.f/7.f);
    out[i*5+2] = o2 * (2.f/7.f);
    out[i*5+3] = o3 * (2.f/7.f);
    out[i*5+4] = o4 * (2.f/7.f);
}

extern "C" void kernel_launch(void* const* d_in, const int* in_sizes, int n_in,
                              void* d_out, int out_size) {
    const float* x    = (const float*)d_in[0];
    const int*   ei   = (const int*)d_in[1];   // int32 (JAX x64 disabled)
    const float* pre  = (const float*)d_in[2];
    const float* conn = (const float*)d_in[3];
    const float* W1   = (const float*)d_in[4];
    const float* b1   = (const float*)d_in[5];
    const float* Ws1  = (const float*)d_in[6];
    const float* W2   = (const float*)d_in[7];
    const float* b2   = (const float*)d_in[8];
    const float* Ws2  = (const float*)d_in[9];
    float* out = (float*)d_out;

    cudaFuncSetAttribute(edge_gemm_tc, cudaFuncAttributeMaxDynamicSharedMemorySize, SMEM_TOT);

    float *y1, *h, *y2, *Wst1, *Wst2;
    unsigned short *Bh1, *Bl1, *Bh2, *Bl2;
    cudaGetSymbolAddress((void**)&y1,   g_y1);
    cudaGetSymbolAddress((void**)&h,    g_h);
    cudaGetSymbolAddress((void**)&y2,   g_y2);
    cudaGetSymbolAddress((void**)&Wst1, g_Wst1);
    cudaGetSymbolAddress((void**)&Wst2, g_Wst2);
    cudaGetSymbolAddress((void**)&Bh1,  g_Bh1);
    cudaGetSymbolAddress((void**)&Bl1,  g_Bl1);
    cudaGetSymbolAddress((void**)&Bh2,  g_Bh2);
    cudaGetSymbolAddress((void**)&Bl2,  g_Bl2);

    // keep ncu's capture ordinal on an edge_gemm_tc launch
    zz_marker<<<1, 32>>>();

    prep_weights<<<(NCHUNK * BCH + 255) / 256, 256>>>(W1, W2, Ws1, Ws2);

    // layer 1
    self_gemm<<<NN / 4, 80>>>(x, Wst1, b1, y1);
    edge_gemm_tc<<<NE / TEB, THR, SMEM_TOT>>>(x, ei, pre, conn, Bh1, Bl1, y1);
    nonlin_kernel<<<(NN * NCH + 127) / 128, 128>>>(y1, nullptr, h);

    // layer 2
    self_gemm<<<NN / 4, 80>>>(h, Wst2, b2, y2);
    edge_gemm_tc<<<NE / TEB, THR, SMEM_TOT>>>(h, ei, pre, conn, Bh2, Bl2, y2);

    // residual + final nonlin -> output
    nonlin_kernel<<<(NN * NCH + 127) / 128, 128>>>(y2, x, out);
}